// round 10
// baseline (speedup 1.0000x reference)
#include <cuda_runtime.h>
#include <cuda_fp16.h>
#include <cstdint>

// GumbelSoftmaxVectorQuantizer — round 10
//   GEMM: fp16 single-term, tile 128x64, 256 threads, 2 CTAs/SM resident
//         (epilogue/prologue of one CTA overlaps mainloop of the other),
//         one barrier per chunk.
//   Softmax: warp-per-group, no smem, butterfly top-2 + exact fp32 fixup.

static constexpr int Mx = 16384;
static constexpr int Kx = 1024;
static constexpr int Nx = 4096;
static constexpr int Vx = 1024;
static constexpr int Dx = 128;
static constexpr float INV_TAU = 0.5f;

__device__ float g_logits[(size_t)Mx * Nx];
__device__ unsigned short g_Ah[(size_t)Mx * Kx];   // fp16 [M][K]
__device__ unsigned short g_Bh[(size_t)Nx * Kx];   // fp16 [N][K] = W^T

__device__ __forceinline__ uint32_t smem_u32(const void* p) {
    uint32_t a;
    asm("{ .reg .u64 t; cvta.to.shared.u64 t, %1; cvt.u32.u64 %0, t; }" : "=r"(a) : "l"(p));
    return a;
}

// ---------------- K0a: convert A to fp16 ----------------
__global__ __launch_bounds__(256)
void split_a_kernel(const float* __restrict__ A) {
    const size_t idx = ((size_t)blockIdx.x * 256 + threadIdx.x) * 8;
    if (idx >= (size_t)Mx * Kx) return;
    float4 a0 = *(const float4*)&A[idx];
    float4 a1 = *(const float4*)&A[idx + 4];
    float v[8] = {a0.x, a0.y, a0.z, a0.w, a1.x, a1.y, a1.z, a1.w};
    unsigned short h[8];
#pragma unroll
    for (int t = 0; t < 8; t++)
        h[t] = __half_as_ushort(__float2half_rn(v[t]));
    uint4 uh;
    uh.x = h[0] | ((uint32_t)h[1] << 16); uh.y = h[2] | ((uint32_t)h[3] << 16);
    uh.z = h[4] | ((uint32_t)h[5] << 16); uh.w = h[6] | ((uint32_t)h[7] << 16);
    *(uint4*)&g_Ah[idx] = uh;
}

// ---------------- K0b: transpose + convert W ----------------
__global__ __launch_bounds__(256)
void split_w_kernel(const float* __restrict__ W) {
    __shared__ float s[64][65];
    const int ct = blockIdx.y;
    const int n0 = blockIdx.x * 64;
    const int k0 = ct * 64;
    const int tid = threadIdx.x;
    for (int i = tid; i < 1024; i += 256) {
        const int kk = i >> 4, n4 = (i & 15) << 2;
        float4 w = *(const float4*)&W[(size_t)(k0 + kk) * Nx + n0 + n4];
        s[kk][n4] = w.x; s[kk][n4 + 1] = w.y; s[kk][n4 + 2] = w.z; s[kk][n4 + 3] = w.w;
    }
    __syncthreads();
    for (int i = tid; i < 512; i += 256) {
        const int nl = i >> 3, j = (i & 7) << 3;
        unsigned short h[8];
#pragma unroll
        for (int t = 0; t < 8; t++)
            h[t] = __half_as_ushort(__float2half_rn(s[j + t][nl]));
        const size_t o = (size_t)(n0 + nl) * Kx + k0 + j;
        uint4 uh;
        uh.x = h[0] | ((uint32_t)h[1] << 16); uh.y = h[2] | ((uint32_t)h[3] << 16);
        uh.z = h[4] | ((uint32_t)h[5] << 16); uh.w = h[6] | ((uint32_t)h[7] << 16);
        *(uint4*)&g_Bh[o] = uh;
    }
}

// ---------------- K1: mma.sync fp16 GEMM (128x64 tile) ----------------
static constexpr int BK = 32;
static constexpr int STAGES = 4;
static constexpr int RSTRIDE = 40;                   // fp16 per row (80B)
static constexpr int ROW_B = 128;                    // smem row where B starts
static constexpr int STAGE_BYTES = 192 * RSTRIDE * 2;   // 15360
static constexpr int SMEM_BYTES = STAGES * STAGE_BYTES; // 61440
static constexpr int NCHUNK = Kx / BK;
static constexpr int NTHREADS = 256;

__device__ __forceinline__ void cp16(uint32_t dst, const void* src) {
    asm volatile("cp.async.cg.shared.global [%0], [%1], 16;" :: "r"(dst), "l"(src) : "memory");
}
__device__ __forceinline__ void cp_commit() {
    asm volatile("cp.async.commit_group;" ::: "memory");
}
__device__ __forceinline__ void cp_wait2() {
    asm volatile("cp.async.wait_group 2;" ::: "memory");
}
__device__ __forceinline__ void ldsm4(uint32_t& r0, uint32_t& r1, uint32_t& r2, uint32_t& r3,
                                      uint32_t addr) {
    asm volatile("ldmatrix.sync.aligned.m8n8.x4.shared.b16 {%0,%1,%2,%3}, [%4];"
                 : "=r"(r0), "=r"(r1), "=r"(r2), "=r"(r3) : "r"(addr));
}
__device__ __forceinline__ void mma_f16(float* c, const uint32_t* a, const uint32_t* b) {
    asm volatile(
        "mma.sync.aligned.m16n8k16.row.col.f32.f16.f16.f32 "
        "{%0,%1,%2,%3}, {%4,%5,%6,%7}, {%8,%9}, {%0,%1,%2,%3};"
        : "+f"(c[0]), "+f"(c[1]), "+f"(c[2]), "+f"(c[3])
        : "r"(a[0]), "r"(a[1]), "r"(a[2]), "r"(a[3]), "r"(b[0]), "r"(b[1]));
}

__global__ __launch_bounds__(NTHREADS, 2)
void gemm_kernel(const float* __restrict__ bias, const float* __restrict__ gum) {
    extern __shared__ char smem[];
    const uint32_t sbase = smem_u32(smem);
    const int tid  = threadIdx.x;
    const int lane = tid & 31;
    const int wid  = tid >> 5;          // 0..7
    const int wm   = wid >> 1;          // 0..3 : 32-row slice
    const int wn   = wid & 1;           // 0..1 : 32-col slice
    const int bm   = blockIdx.y * 128;
    const int bn   = blockIdx.x * 64;

    const unsigned short* srcAh = g_Ah + (size_t)bm * Kx;
    const unsigned short* srcBh = g_Bh + (size_t)bn * Kx;

    // per stage: A rows 0..127, B rows 128..191; 4x16B per row
    auto issue_stage = [&](int chunk) {
        const int s = chunk & (STAGES - 1);
        const uint32_t stb = sbase + s * STAGE_BYTES;
        const int r = tid >> 2;          // 0..63
        const int c = tid & 3;
        const uint32_t doff = (uint32_t)(c * 16);
        const size_t soff = (size_t)chunk * BK + c * 8;
        cp16(stb + (r)            * 80 + doff, srcAh + (size_t)(r)       * Kx + soff);
        cp16(stb + (r + 64)       * 80 + doff, srcAh + (size_t)(r + 64)  * Kx + soff);
        cp16(stb + (r + ROW_B)    * 80 + doff, srcBh + (size_t)(r)       * Kx + soff);
        cp_commit();
    };

    float acc[2][4][4];
#pragma unroll
    for (int i = 0; i < 2; i++)
#pragma unroll
        for (int j = 0; j < 4; j++)
#pragma unroll
            for (int q = 0; q < 4; q++) acc[i][j][q] = 0.f;

    issue_stage(0); issue_stage(1); issue_stage(2);

    const int lrow = lane & 15;
    const int lcol = (lane >> 4) * 8;

#pragma unroll 1
    for (int ch = 0; ch < NCHUNK; ch++) {
        cp_wait2();
        __syncthreads();                 // single barrier per chunk
        if (ch + 3 < NCHUNK) issue_stage(ch + 3);

        const uint32_t stb = sbase + (ch & (STAGES - 1)) * STAGE_BYTES;

#pragma unroll
        for (int ks = 0; ks < 2; ks++) {
            const int kk = ks * 16;
            uint32_t ah[2][4], bh[4][2];
#pragma unroll
            for (int mf = 0; mf < 2; mf++) {
                const int row = wm * 32 + mf * 16 + lrow;
                const uint32_t off = (uint32_t)(row * RSTRIDE + kk + lcol) * 2;
                ldsm4(ah[mf][0], ah[mf][1], ah[mf][2], ah[mf][3], stb + off);
            }
#pragma unroll
            for (int np = 0; np < 2; np++) {
                const int row = ROW_B + wn * 32 + np * 16 + lrow;
                const uint32_t off = (uint32_t)(row * RSTRIDE + kk + lcol) * 2;
                uint32_t r0, r1, r2, r3;
                ldsm4(r0, r1, r2, r3, stb + off);
                bh[2 * np][0] = r0; bh[2 * np][1] = r2;
                bh[2 * np + 1][0] = r1; bh[2 * np + 1][1] = r3;
            }
#pragma unroll
            for (int mf = 0; mf < 2; mf++)
#pragma unroll
                for (int nf = 0; nf < 4; nf++)
                    mma_f16(acc[mf][nf], ah[mf], bh[nf]);
        }
    }

    // epilogue: (acc + bias + gumbel) * INV_TAU -> g_logits
    const int er = lane >> 2;
    const int ec = (lane & 3) * 2;
#pragma unroll
    for (int mf = 0; mf < 2; mf++) {
#pragma unroll
        for (int nf = 0; nf < 4; nf++) {
            const int col = bn + wn * 32 + nf * 8 + ec;
            const float2 bb = *(const float2*)&bias[col];
#pragma unroll
            for (int h = 0; h < 2; h++) {
                const int row = bm + wm * 32 + mf * 16 + er + h * 8;
                const size_t go = (size_t)row * Nx + col;
                const float2 g = *(const float2*)&gum[go];
                float2 o;
                o.x = (acc[mf][nf][2 * h]     + bb.x + g.x) * INV_TAU;
                o.y = (acc[mf][nf][2 * h + 1] + bb.y + g.y) * INV_TAU;
                *(float2*)&g_logits[go] = o;
            }
        }
    }
}

// ---------------- K2: warp-per-group softmax + argmax ----------------
__global__ __launch_bounds__(256)
void softmax_kernel(const int*   __restrict__ pads,
                    const float* __restrict__ codebook,
                    const float* __restrict__ A,
                    const float* __restrict__ W,
                    const float* __restrict__ bias,
                    const float* __restrict__ gum,
                    float*       __restrict__ ids_out,
                    float*       __restrict__ quant_out,
                    float*       __restrict__ probs_out)
{
    const int warp = threadIdx.x >> 5;
    const int lane = threadIdx.x & 31;
    const int grp  = blockIdx.x * 8 + warp;
    const int row  = grp >> 2;
    const int g    = grp & 3;

    const float* base = g_logits + (size_t)grp * Vx;

    float4 v4[8];
#pragma unroll
    for (int j = 0; j < 8; j++)
        v4[j] = *(const float4*)&base[j * 128 + lane * 4];

    // lane-local top-2 (indices ascending -> first-occurrence ties)
    float m1 = -3.4e38f, m2 = -3.4e38f;
    int i1 = -1, i2 = -1;
#pragma unroll
    for (int j = 0; j < 8; j++) {
        const float vv[4] = {v4[j].x, v4[j].y, v4[j].z, v4[j].w};
#pragma unroll
        for (int q = 0; q < 4; q++) {
            const int ii = j * 128 + lane * 4 + q;
            if (vv[q] > m1) { m2 = m1; i2 = i1; m1 = vv[q]; i1 = ii; }
            else if (vv[q] > m2) { m2 = vv[q]; i2 = ii; }
        }
    }
    // butterfly top-2 merge (all lanes converge)
#pragma unroll
    for (int off = 16; off > 0; off >>= 1) {
        float o1 = __shfl_xor_sync(0xffffffffu, m1, off);
        int   oi1 = __shfl_xor_sync(0xffffffffu, i1, off);
        float o2 = __shfl_xor_sync(0xffffffffu, m2, off);
        int   oi2 = __shfl_xor_sync(0xffffffffu, i2, off);
        if (o1 > m1 || (o1 == m1 && oi1 < i1)) {
            const bool k = (m1 > o2 || (m1 == o2 && i1 < oi2));
            m2 = k ? m1 : o2; i2 = k ? i1 : oi2;
            m1 = o1; i1 = oi1;
        } else if (o1 > m2 || (o1 == m2 && oi1 < i2)) {
            m2 = o1; i2 = oi1;
        }
    }

    const int pad = pads[row];
    int id = i1;

    // exact fp32 recompute of near-tie candidates (rare)
    if ((m1 - m2 < 3e-3f) && !pad) {
        const float* arow = A + (size_t)row * Kx;
        float fixv[2];
#pragma unroll 1
        for (int cidx = 0; cidx < 2; cidx++) {
            const int vv = (cidx == 0) ? i1 : i2;
            const int col = (g << 10) + vv;
            float part = 0.f;
#pragma unroll
            for (int j = 0; j < 32; j++) {
                const int k = j * 32 + lane;
                part = fmaf(arow[k], W[(size_t)k * Nx + col], part);
            }
#pragma unroll
            for (int off = 16; off > 0; off >>= 1)
                part += __shfl_xor_sync(0xffffffffu, part, off);
            fixv[cidx] = (part + bias[col] + gum[(size_t)grp * Vx + vv]) * INV_TAU;
        }
        id = (fixv[1] > fixv[0] || (fixv[1] == fixv[0] && i2 < i1)) ? i2 : i1;
    }

    // exp + sum (overwrite v4 with exps)
    float s = 0.f;
#pragma unroll
    for (int j = 0; j < 8; j++) {
        v4[j].x = __expf(v4[j].x - m1); s += v4[j].x;
        v4[j].y = __expf(v4[j].y - m1); s += v4[j].y;
        v4[j].z = __expf(v4[j].z - m1); s += v4[j].z;
        v4[j].w = __expf(v4[j].w - m1); s += v4[j].w;
    }
#pragma unroll
    for (int off = 16; off > 0; off >>= 1)
        s += __shfl_xor_sync(0xffffffffu, s, off);

    const float inv = pad ? 0.f : (1.f / s);
    float* pout = probs_out + (size_t)grp * Vx;
#pragma unroll
    for (int j = 0; j < 8; j++) {
        float4 p;
        p.x = v4[j].x * inv; p.y = v4[j].y * inv;
        p.z = v4[j].z * inv; p.w = v4[j].w * inv;
        *(float4*)&pout[j * 128 + lane * 4] = p;
    }

    // quantized: 128 dims, 4 per lane (float4)
    float4 q;
    if (pad) { q = make_float4(0.f, 0.f, 0.f, 0.f); }
    else     { q = *(const float4*)&codebook[(size_t)(((g << 10) + id) << 7) + lane * 4]; }
    *(float4*)&quant_out[(size_t)row * 512 + g * 128 + lane * 4] = q;

    if (lane == 0) ids_out[grp] = pad ? -1.0f : (float)id;
}

// ---------------- launch ----------------
extern "C" void kernel_launch(void* const* d_in, const int* in_sizes, int n_in,
                              void* d_out, int out_size)
{
    const float* inputs = (const float*)d_in[0];
    const int*   pads   = (const int*)  d_in[1];
    const float* gum    = (const float*)d_in[2];
    const float* W      = (const float*)d_in[3];
    const float* bias   = (const float*)d_in[4];
    const float* cb     = (const float*)d_in[5];

    float* out       = (float*)d_out;
    float* ids_out   = out;
    float* quant_out = out + (size_t)Mx * 4;
    float* probs_out = quant_out + (size_t)Mx * 4 * Dx;

    cudaFuncSetAttribute(gemm_kernel, cudaFuncAttributeMaxDynamicSharedMemorySize, SMEM_BYTES);

    split_a_kernel<<<(Mx * Kx / 8 + 255) / 256, 256>>>(inputs);
    dim3 wg(Nx / 64, Kx / 64);
    split_w_kernel<<<wg, 256>>>(W);
    dim3 grid(Nx / 64, Mx / 128);
    gemm_kernel<<<grid, NTHREADS, SMEM_BYTES>>>(bias, gum);
    softmax_kernel<<<Mx * 4 / 8, 256>>>(pads, cb, inputs, W, bias, gum,
                                        ids_out, quant_out, probs_out);
}

// round 11
// speedup vs baseline: 1.0984x; 1.0984x over previous
#include <cuda_runtime.h>
#include <cuda_fp16.h>
#include <cstdint>

// GumbelSoftmaxVectorQuantizer — round 11
//   GEMM: fp16 single-term, tile 128x64, BK=64 (16 chunks, half the barriers),
//         3-stage cp.async, 2 CTAs/SM. Softmax: reverted to round-9 shape
//         (128-thread block, 94% occ) — round-10 warp version was reg-bound.

static constexpr int Mx = 16384;
static constexpr int Kx = 1024;
static constexpr int Nx = 4096;
static constexpr int Vx = 1024;
static constexpr int Dx = 128;
static constexpr float INV_TAU = 0.5f;

__device__ float g_logits[(size_t)Mx * Nx];
__device__ unsigned short g_Ah[(size_t)Mx * Kx];   // fp16 [M][K]
__device__ unsigned short g_Bh[(size_t)Nx * Kx];   // fp16 [N][K] = W^T

__device__ __forceinline__ uint32_t smem_u32(const void* p) {
    uint32_t a;
    asm("{ .reg .u64 t; cvta.to.shared.u64 t, %1; cvt.u32.u64 %0, t; }" : "=r"(a) : "l"(p));
    return a;
}

// ---------------- K0a: convert A to fp16 ----------------
__global__ __launch_bounds__(256)
void split_a_kernel(const float* __restrict__ A) {
    const size_t idx = ((size_t)blockIdx.x * 256 + threadIdx.x) * 8;
    if (idx >= (size_t)Mx * Kx) return;
    float4 a0 = *(const float4*)&A[idx];
    float4 a1 = *(const float4*)&A[idx + 4];
    float v[8] = {a0.x, a0.y, a0.z, a0.w, a1.x, a1.y, a1.z, a1.w};
    unsigned short h[8];
#pragma unroll
    for (int t = 0; t < 8; t++)
        h[t] = __half_as_ushort(__float2half_rn(v[t]));
    uint4 uh;
    uh.x = h[0] | ((uint32_t)h[1] << 16); uh.y = h[2] | ((uint32_t)h[3] << 16);
    uh.z = h[4] | ((uint32_t)h[5] << 16); uh.w = h[6] | ((uint32_t)h[7] << 16);
    *(uint4*)&g_Ah[idx] = uh;
}

// ---------------- K0b: transpose + convert W ----------------
__global__ __launch_bounds__(256)
void split_w_kernel(const float* __restrict__ W) {
    __shared__ float s[64][65];
    const int ct = blockIdx.y;
    const int n0 = blockIdx.x * 64;
    const int k0 = ct * 64;
    const int tid = threadIdx.x;
    for (int i = tid; i < 1024; i += 256) {
        const int kk = i >> 4, n4 = (i & 15) << 2;
        float4 w = *(const float4*)&W[(size_t)(k0 + kk) * Nx + n0 + n4];
        s[kk][n4] = w.x; s[kk][n4 + 1] = w.y; s[kk][n4 + 2] = w.z; s[kk][n4 + 3] = w.w;
    }
    __syncthreads();
    for (int i = tid; i < 512; i += 256) {
        const int nl = i >> 3, j = (i & 7) << 3;
        unsigned short h[8];
#pragma unroll
        for (int t = 0; t < 8; t++)
            h[t] = __half_as_ushort(__float2half_rn(s[j + t][nl]));
        const size_t o = (size_t)(n0 + nl) * Kx + k0 + j;
        uint4 uh;
        uh.x = h[0] | ((uint32_t)h[1] << 16); uh.y = h[2] | ((uint32_t)h[3] << 16);
        uh.z = h[4] | ((uint32_t)h[5] << 16); uh.w = h[6] | ((uint32_t)h[7] << 16);
        *(uint4*)&g_Bh[o] = uh;
    }
}

// ---------------- K1: mma.sync fp16 GEMM (128x64 tile, BK=64) ----------------
static constexpr int BK = 64;
static constexpr int STAGES = 3;
static constexpr int RSTRIDE = 72;                    // fp16 per row (144B = 9*16)
static constexpr int ROW_B = 128;
static constexpr int STAGE_BYTES = 192 * RSTRIDE * 2; // 27648
static constexpr int SMEM_BYTES = STAGES * STAGE_BYTES; // 82944
static constexpr int NCHUNK = Kx / BK;                // 16
static constexpr int NTHREADS = 256;

__device__ __forceinline__ void cp16(uint32_t dst, const void* src) {
    asm volatile("cp.async.cg.shared.global [%0], [%1], 16;" :: "r"(dst), "l"(src) : "memory");
}
__device__ __forceinline__ void cp_commit() {
    asm volatile("cp.async.commit_group;" ::: "memory");
}
__device__ __forceinline__ void cp_wait1() {
    asm volatile("cp.async.wait_group 1;" ::: "memory");
}
__device__ __forceinline__ void ldsm4(uint32_t& r0, uint32_t& r1, uint32_t& r2, uint32_t& r3,
                                      uint32_t addr) {
    asm volatile("ldmatrix.sync.aligned.m8n8.x4.shared.b16 {%0,%1,%2,%3}, [%4];"
                 : "=r"(r0), "=r"(r1), "=r"(r2), "=r"(r3) : "r"(addr));
}
__device__ __forceinline__ void mma_f16(float* c, const uint32_t* a, const uint32_t* b) {
    asm volatile(
        "mma.sync.aligned.m16n8k16.row.col.f32.f16.f16.f32 "
        "{%0,%1,%2,%3}, {%4,%5,%6,%7}, {%8,%9}, {%0,%1,%2,%3};"
        : "+f"(c[0]), "+f"(c[1]), "+f"(c[2]), "+f"(c[3])
        : "r"(a[0]), "r"(a[1]), "r"(a[2]), "r"(a[3]), "r"(b[0]), "r"(b[1]));
}

__global__ __launch_bounds__(NTHREADS, 2)
void gemm_kernel(const float* __restrict__ bias, const float* __restrict__ gum) {
    extern __shared__ char smem[];
    const uint32_t sbase = smem_u32(smem);
    const int tid  = threadIdx.x;
    const int lane = tid & 31;
    const int wid  = tid >> 5;          // 0..7
    const int wm   = wid >> 1;          // 0..3
    const int wn   = wid & 1;           // 0..1
    const int bm   = blockIdx.y * 128;
    const int bn   = blockIdx.x * 64;

    const unsigned short* srcAh = g_Ah + (size_t)bm * Kx;
    const unsigned short* srcBh = g_Bh + (size_t)bn * Kx;

    // per stage: 192 rows x 128B of data (8 x 16B per row); 6 cp16/thread
    auto issue_stage = [&](int chunk) {
        const int s = chunk % STAGES;
        const uint32_t stb = sbase + s * STAGE_BYTES;
        const size_t kof = (size_t)chunk * BK;
        // i = 0..3 : A rows (idx < 1024 -> r < 128)
#pragma unroll
        for (int i = 0; i < 4; i++) {
            const int idx = tid + i * 256;
            const int r = idx >> 3, c = idx & 7;
            cp16(stb + (uint32_t)(r * 144 + c * 16),
                 srcAh + (size_t)r * Kx + kof + c * 8);
        }
        // i = 4,5 : B rows (r = 128..191)
#pragma unroll
        for (int i = 4; i < 6; i++) {
            const int idx = tid + i * 256;
            const int r = idx >> 3, c = idx & 7;
            cp16(stb + (uint32_t)(r * 144 + c * 16),
                 srcBh + (size_t)(r - 128) * Kx + kof + c * 8);
        }
        cp_commit();
    };

    float acc[2][4][4];
#pragma unroll
    for (int i = 0; i < 2; i++)
#pragma unroll
        for (int j = 0; j < 4; j++)
#pragma unroll
            for (int q = 0; q < 4; q++) acc[i][j][q] = 0.f;

    issue_stage(0); issue_stage(1);

    const int lrow = lane & 15;
    const int lcol = (lane >> 4) * 8;

#pragma unroll 1
    for (int ch = 0; ch < NCHUNK; ch++) {
        cp_wait1();
        __syncthreads();
        if (ch + 2 < NCHUNK) issue_stage(ch + 2);

        const uint32_t stb = sbase + (ch % STAGES) * STAGE_BYTES;

#pragma unroll
        for (int ks = 0; ks < 4; ks++) {
            const int kk = ks * 16;
            uint32_t ah[2][4], bh[4][2];
#pragma unroll
            for (int mf = 0; mf < 2; mf++) {
                const int row = wm * 32 + mf * 16 + lrow;
                const uint32_t off = (uint32_t)(row * RSTRIDE + kk + lcol) * 2;
                ldsm4(ah[mf][0], ah[mf][1], ah[mf][2], ah[mf][3], stb + off);
            }
#pragma unroll
            for (int np = 0; np < 2; np++) {
                const int row = ROW_B + wn * 32 + np * 16 + lrow;
                const uint32_t off = (uint32_t)(row * RSTRIDE + kk + lcol) * 2;
                uint32_t r0, r1, r2, r3;
                ldsm4(r0, r1, r2, r3, stb + off);
                bh[2 * np][0] = r0; bh[2 * np][1] = r2;
                bh[2 * np + 1][0] = r1; bh[2 * np + 1][1] = r3;
            }
#pragma unroll
            for (int mf = 0; mf < 2; mf++)
#pragma unroll
                for (int nf = 0; nf < 4; nf++)
                    mma_f16(acc[mf][nf], ah[mf], bh[nf]);
        }
    }

    // epilogue: (acc + bias + gumbel) * INV_TAU -> g_logits
    const int er = lane >> 2;
    const int ec = (lane & 3) * 2;
#pragma unroll
    for (int mf = 0; mf < 2; mf++) {
#pragma unroll
        for (int nf = 0; nf < 4; nf++) {
            const int col = bn + wn * 32 + nf * 8 + ec;
            const float2 bb = *(const float2*)&bias[col];
#pragma unroll
            for (int h = 0; h < 2; h++) {
                const int row = bm + wm * 32 + mf * 16 + er + h * 8;
                const size_t go = (size_t)row * Nx + col;
                const float2 g = *(const float2*)&gum[go];
                float2 o;
                o.x = (acc[mf][nf][2 * h]     + bb.x + g.x) * INV_TAU;
                o.y = (acc[mf][nf][2 * h + 1] + bb.y + g.y) * INV_TAU;
                *(float2*)&g_logits[go] = o;
            }
        }
    }
}

// ---------------- K2: softmax + argmax (round-9 shape) ----------------
__global__ __launch_bounds__(128)
void softmax_kernel(const int*   __restrict__ pads,
                    const float* __restrict__ codebook,
                    const float* __restrict__ A,
                    const float* __restrict__ W,
                    const float* __restrict__ bias,
                    const float* __restrict__ gum,
                    float*       __restrict__ ids_out,
                    float*       __restrict__ quant_out,
                    float*       __restrict__ probs_out)
{
    const int grp  = blockIdx.x;
    const int row  = grp >> 2;
    const int g    = grp & 3;
    const int tid  = threadIdx.x;
    const int lane = tid & 31;
    const int warp = tid >> 5;

    const float* base = g_logits + (size_t)grp * Vx;

    float v[8];
    *(float4*)&v[0] = *(const float4*)&base[tid * 8];
    *(float4*)&v[4] = *(const float4*)&base[tid * 8 + 4];

    float m1 = v[0], m2 = -3.4e38f;
    int i1 = tid * 8, i2 = -1;
#pragma unroll
    for (int j = 1; j < 8; j++) {
        const int ii = tid * 8 + j;
        if (v[j] > m1) { m2 = m1; i2 = i1; m1 = v[j]; i1 = ii; }
        else if (v[j] > m2) { m2 = v[j]; i2 = ii; }
    }
#pragma unroll
    for (int off = 16; off > 0; off >>= 1) {
        float o1 = __shfl_down_sync(0xffffffffu, m1, off);
        int   oi1 = __shfl_down_sync(0xffffffffu, i1, off);
        float o2 = __shfl_down_sync(0xffffffffu, m2, off);
        int   oi2 = __shfl_down_sync(0xffffffffu, i2, off);
        if (o1 > m1 || (o1 == m1 && oi1 < i1)) {
            float t2 = (m1 > o2 || (m1 == o2 && i1 < oi2)) ? m1 : o2;
            int   ti2 = (m1 > o2 || (m1 == o2 && i1 < oi2)) ? i1 : oi2;
            m1 = o1; i1 = oi1; m2 = t2; i2 = ti2;
        } else {
            if (o1 > m2 || (o1 == m2 && oi1 < i2)) { m2 = o1; i2 = oi1; }
        }
    }

    __shared__ float sw1[4], sw2[4], ssum[4];
    __shared__ int   si1[4], si2[4];
    __shared__ float red_m, red_s, sfix[2];
    __shared__ int   red_i, cand1, cand2, need_fix;

    if (lane == 0) { sw1[warp] = m1; si1[warp] = i1; sw2[warp] = m2; si2[warp] = i2; }
    __syncthreads();
    if (tid == 0) {
        float b1 = sw1[0], b2 = sw2[0]; int j1 = si1[0], j2 = si2[0];
        for (int w = 1; w < 4; w++) {
            float o1 = sw1[w], o2 = sw2[w]; int oi1 = si1[w], oi2 = si2[w];
            if (o1 > b1 || (o1 == b1 && oi1 < j1)) {
                float t2 = (b1 > o2 || (b1 == o2 && j1 < oi2)) ? b1 : o2;
                int   ti2 = (b1 > o2 || (b1 == o2 && j1 < oi2)) ? j1 : oi2;
                b1 = o1; j1 = oi1; b2 = t2; j2 = ti2;
            } else if (o1 > b2 || (o1 == b2 && oi1 < j2)) { b2 = o1; j2 = oi1; }
        }
        red_m = b1; red_i = j1; cand1 = j1; cand2 = j2;
        need_fix = (b1 - b2 < 3e-3f) ? 1 : 0;
    }
    __syncthreads();

    const int pad = pads[row];

    if (need_fix && !pad) {
        const float* arow = A + (size_t)row * Kx;
        for (int cidx = 0; cidx < 2; cidx++) {
            const int vv = (cidx == 0) ? cand1 : cand2;
            const int col = (g << 10) + vv;
            float part = 0.f;
#pragma unroll
            for (int j = 0; j < 8; j++) {
                const int k = tid * 8 + j;
                part = fmaf(arow[k], W[(size_t)k * Nx + col], part);
            }
#pragma unroll
            for (int off = 16; off > 0; off >>= 1)
                part += __shfl_down_sync(0xffffffffu, part, off);
            if (lane == 0) ssum[warp] = part;
            __syncthreads();
            if (tid == 0) {
                float tot = ssum[0] + ssum[1] + ssum[2] + ssum[3];
                sfix[cidx] = (tot + bias[col] + gum[(size_t)grp * Vx + vv]) * INV_TAU;
            }
            __syncthreads();
        }
        if (tid == 0) {
            const float v1 = sfix[0], v2 = sfix[1];
            red_i = (v2 > v1 || (v2 == v1 && cand2 < cand1)) ? cand2 : cand1;
        }
        __syncthreads();
    }

    const float mx = red_m;
    float e[8]; float s = 0.f;
#pragma unroll
    for (int j = 0; j < 8; j++) { e[j] = __expf(v[j] - mx); s += e[j]; }
#pragma unroll
    for (int off = 16; off > 0; off >>= 1)
        s += __shfl_down_sync(0xffffffffu, s, off);
    if (lane == 0) ssum[warp] = s;
    __syncthreads();
    if (tid == 0) red_s = ssum[0] + ssum[1] + ssum[2] + ssum[3];
    __syncthreads();

    const float inv = pad ? 0.f : (1.f / red_s);
    float4 p0, p1;
    p0.x = e[0] * inv; p0.y = e[1] * inv; p0.z = e[2] * inv; p0.w = e[3] * inv;
    p1.x = e[4] * inv; p1.y = e[5] * inv; p1.z = e[6] * inv; p1.w = e[7] * inv;
    *(float4*)&probs_out[(size_t)grp * Vx + tid * 8]     = p0;
    *(float4*)&probs_out[(size_t)grp * Vx + tid * 8 + 4] = p1;

    const int id = red_i;
    const float q = pad ? 0.f : codebook[(((g << 10) + id) << 7) + tid];
    quant_out[(size_t)row * (4 * Dx) + g * Dx + tid] = q;
    if (tid == 0) ids_out[grp] = pad ? -1.0f : (float)id;
}

// ---------------- launch ----------------
extern "C" void kernel_launch(void* const* d_in, const int* in_sizes, int n_in,
                              void* d_out, int out_size)
{
    const float* inputs = (const float*)d_in[0];
    const int*   pads   = (const int*)  d_in[1];
    const float* gum    = (const float*)d_in[2];
    const float* W      = (const float*)d_in[3];
    const float* bias   = (const float*)d_in[4];
    const float* cb     = (const float*)d_in[5];

    float* out       = (float*)d_out;
    float* ids_out   = out;
    float* quant_out = out + (size_t)Mx * 4;
    float* probs_out = quant_out + (size_t)Mx * 4 * Dx;

    cudaFuncSetAttribute(gemm_kernel, cudaFuncAttributeMaxDynamicSharedMemorySize, SMEM_BYTES);

    split_a_kernel<<<(Mx * Kx / 8 + 255) / 256, 256>>>(inputs);
    dim3 wg(Nx / 64, Kx / 64);
    split_w_kernel<<<wg, 256>>>(W);
    dim3 grid(Nx / 64, Mx / 128);
    gemm_kernel<<<grid, NTHREADS, SMEM_BYTES>>>(bias, gum);
    softmax_kernel<<<Mx * 4, 128>>>(pads, cb, inputs, W, bias, gum,
                                    ids_out, quant_out, probs_out);
}

// round 13
// speedup vs baseline: 1.1002x; 1.0016x over previous
#include <cuda_runtime.h>
#include <cuda_fp16.h>
#include <cstdint>

// GumbelSoftmaxVectorQuantizer — round 12
//   Same GEMM as round 11 (fp16 single-term, 128x64, BK=64, 2 CTAs/SM)
//   but the logits staging buffer is fp16: halves the 512MB scratch
//   round-trip. Argmax fixup threshold widened to 6e-3 (12 sigma of the
//   fp16-storage + GEMM error) -> ids stay exact via fp32 recompute.

static constexpr int Mx = 16384;
static constexpr int Kx = 1024;
static constexpr int Nx = 4096;
static constexpr int Vx = 1024;
static constexpr int Dx = 128;
static constexpr float INV_TAU = 0.5f;

__device__ __half g_logits[(size_t)Mx * Nx];       // fp16 staging (128MB)
__device__ unsigned short g_Ah[(size_t)Mx * Kx];   // fp16 [M][K]
__device__ unsigned short g_Bh[(size_t)Nx * Kx];   // fp16 [N][K] = W^T

__device__ __forceinline__ uint32_t smem_u32(const void* p) {
    uint32_t a;
    asm("{ .reg .u64 t; cvta.to.shared.u64 t, %1; cvt.u32.u64 %0, t; }" : "=r"(a) : "l"(p));
    return a;
}

// ---------------- K0a: convert A to fp16 ----------------
__global__ __launch_bounds__(256)
void split_a_kernel(const float* __restrict__ A) {
    const size_t idx = ((size_t)blockIdx.x * 256 + threadIdx.x) * 8;
    if (idx >= (size_t)Mx * Kx) return;
    float4 a0 = *(const float4*)&A[idx];
    float4 a1 = *(const float4*)&A[idx + 4];
    float v[8] = {a0.x, a0.y, a0.z, a0.w, a1.x, a1.y, a1.z, a1.w};
    unsigned short h[8];
#pragma unroll
    for (int t = 0; t < 8; t++)
        h[t] = __half_as_ushort(__float2half_rn(v[t]));
    uint4 uh;
    uh.x = h[0] | ((uint32_t)h[1] << 16); uh.y = h[2] | ((uint32_t)h[3] << 16);
    uh.z = h[4] | ((uint32_t)h[5] << 16); uh.w = h[6] | ((uint32_t)h[7] << 16);
    *(uint4*)&g_Ah[idx] = uh;
}

// ---------------- K0b: transpose + convert W ----------------
__global__ __launch_bounds__(256)
void split_w_kernel(const float* __restrict__ W) {
    __shared__ float s[64][65];
    const int ct = blockIdx.y;
    const int n0 = blockIdx.x * 64;
    const int k0 = ct * 64;
    const int tid = threadIdx.x;
    for (int i = tid; i < 1024; i += 256) {
        const int kk = i >> 4, n4 = (i & 15) << 2;
        float4 w = *(const float4*)&W[(size_t)(k0 + kk) * Nx + n0 + n4];
        s[kk][n4] = w.x; s[kk][n4 + 1] = w.y; s[kk][n4 + 2] = w.z; s[kk][n4 + 3] = w.w;
    }
    __syncthreads();
    for (int i = tid; i < 512; i += 256) {
        const int nl = i >> 3, j = (i & 7) << 3;
        unsigned short h[8];
#pragma unroll
        for (int t = 0; t < 8; t++)
            h[t] = __half_as_ushort(__float2half_rn(s[j + t][nl]));
        const size_t o = (size_t)(n0 + nl) * Kx + k0 + j;
        uint4 uh;
        uh.x = h[0] | ((uint32_t)h[1] << 16); uh.y = h[2] | ((uint32_t)h[3] << 16);
        uh.z = h[4] | ((uint32_t)h[5] << 16); uh.w = h[6] | ((uint32_t)h[7] << 16);
        *(uint4*)&g_Bh[o] = uh;
    }
}

// ---------------- K1: mma.sync fp16 GEMM (128x64 tile, BK=64) ----------------
static constexpr int BK = 64;
static constexpr int STAGES = 3;
static constexpr int RSTRIDE = 72;                    // fp16 per row (144B)
static constexpr int ROW_B = 128;
static constexpr int STAGE_BYTES = 192 * RSTRIDE * 2; // 27648
static constexpr int SMEM_BYTES = STAGES * STAGE_BYTES; // 82944
static constexpr int NCHUNK = Kx / BK;                // 16
static constexpr int NTHREADS = 256;

__device__ __forceinline__ void cp16(uint32_t dst, const void* src) {
    asm volatile("cp.async.cg.shared.global [%0], [%1], 16;" :: "r"(dst), "l"(src) : "memory");
}
__device__ __forceinline__ void cp_commit() {
    asm volatile("cp.async.commit_group;" ::: "memory");
}
__device__ __forceinline__ void cp_wait1() {
    asm volatile("cp.async.wait_group 1;" ::: "memory");
}
__device__ __forceinline__ void ldsm4(uint32_t& r0, uint32_t& r1, uint32_t& r2, uint32_t& r3,
                                      uint32_t addr) {
    asm volatile("ldmatrix.sync.aligned.m8n8.x4.shared.b16 {%0,%1,%2,%3}, [%4];"
                 : "=r"(r0), "=r"(r1), "=r"(r2), "=r"(r3) : "r"(addr));
}
__device__ __forceinline__ void mma_f16(float* c, const uint32_t* a, const uint32_t* b) {
    asm volatile(
        "mma.sync.aligned.m16n8k16.row.col.f32.f16.f16.f32 "
        "{%0,%1,%2,%3}, {%4,%5,%6,%7}, {%8,%9}, {%0,%1,%2,%3};"
        : "+f"(c[0]), "+f"(c[1]), "+f"(c[2]), "+f"(c[3])
        : "r"(a[0]), "r"(a[1]), "r"(a[2]), "r"(a[3]), "r"(b[0]), "r"(b[1]));
}

__global__ __launch_bounds__(NTHREADS, 2)
void gemm_kernel(const float* __restrict__ bias, const float* __restrict__ gum) {
    extern __shared__ char smem[];
    const uint32_t sbase = smem_u32(smem);
    const int tid  = threadIdx.x;
    const int lane = tid & 31;
    const int wid  = tid >> 5;
    const int wm   = wid >> 1;
    const int wn   = wid & 1;
    const int bm   = blockIdx.y * 128;
    const int bn   = blockIdx.x * 64;

    const unsigned short* srcAh = g_Ah + (size_t)bm * Kx;
    const unsigned short* srcBh = g_Bh + (size_t)bn * Kx;

    auto issue_stage = [&](int chunk) {
        const int s = chunk % STAGES;
        const uint32_t stb = sbase + s * STAGE_BYTES;
        const size_t kof = (size_t)chunk * BK;
#pragma unroll
        for (int i = 0; i < 4; i++) {
            const int idx = tid + i * 256;
            const int r = idx >> 3, c = idx & 7;
            cp16(stb + (uint32_t)(r * 144 + c * 16),
                 srcAh + (size_t)r * Kx + kof + c * 8);
        }
#pragma unroll
        for (int i = 4; i < 6; i++) {
            const int idx = tid + i * 256;
            const int r = idx >> 3, c = idx & 7;
            cp16(stb + (uint32_t)(r * 144 + c * 16),
                 srcBh + (size_t)(r - 128) * Kx + kof + c * 8);
        }
        cp_commit();
    };

    float acc[2][4][4];
#pragma unroll
    for (int i = 0; i < 2; i++)
#pragma unroll
        for (int j = 0; j < 4; j++)
#pragma unroll
            for (int q = 0; q < 4; q++) acc[i][j][q] = 0.f;

    issue_stage(0); issue_stage(1);

    const int lrow = lane & 15;
    const int lcol = (lane >> 4) * 8;

#pragma unroll 1
    for (int ch = 0; ch < NCHUNK; ch++) {
        cp_wait1();
        __syncthreads();
        if (ch + 2 < NCHUNK) issue_stage(ch + 2);

        const uint32_t stb = sbase + (ch % STAGES) * STAGE_BYTES;

#pragma unroll
        for (int ks = 0; ks < 4; ks++) {
            const int kk = ks * 16;
            uint32_t ah[2][4], bh[4][2];
#pragma unroll
            for (int mf = 0; mf < 2; mf++) {
                const int row = wm * 32 + mf * 16 + lrow;
                const uint32_t off = (uint32_t)(row * RSTRIDE + kk + lcol) * 2;
                ldsm4(ah[mf][0], ah[mf][1], ah[mf][2], ah[mf][3], stb + off);
            }
#pragma unroll
            for (int np = 0; np < 2; np++) {
                const int row = ROW_B + wn * 32 + np * 16 + lrow;
                const uint32_t off = (uint32_t)(row * RSTRIDE + kk + lcol) * 2;
                uint32_t r0, r1, r2, r3;
                ldsm4(r0, r1, r2, r3, stb + off);
                bh[2 * np][0] = r0; bh[2 * np][1] = r2;
                bh[2 * np + 1][0] = r1; bh[2 * np + 1][1] = r3;
            }
#pragma unroll
            for (int mf = 0; mf < 2; mf++)
#pragma unroll
                for (int nf = 0; nf < 4; nf++)
                    mma_f16(acc[mf][nf], ah[mf], bh[nf]);
        }
    }

    // epilogue: (acc + bias + gumbel) * INV_TAU -> g_logits (fp16)
    const int er = lane >> 2;
    const int ec = (lane & 3) * 2;
#pragma unroll
    for (int mf = 0; mf < 2; mf++) {
#pragma unroll
        for (int nf = 0; nf < 4; nf++) {
            const int col = bn + wn * 32 + nf * 8 + ec;
            const float2 bb = *(const float2*)&bias[col];
#pragma unroll
            for (int h = 0; h < 2; h++) {
                const int row = bm + wm * 32 + mf * 16 + er + h * 8;
                const size_t go = (size_t)row * Nx + col;
                const float2 g = *(const float2*)&gum[go];
                const float ox = (acc[mf][nf][2 * h]     + bb.x + g.x) * INV_TAU;
                const float oy = (acc[mf][nf][2 * h + 1] + bb.y + g.y) * INV_TAU;
                *(__half2*)&g_logits[go] = __floats2half2_rn(ox, oy);
            }
        }
    }
}

// ---------------- K2: softmax + argmax (fp16 logit reads) ----------------
__global__ __launch_bounds__(128)
void softmax_kernel(const int*   __restrict__ pads,
                    const float* __restrict__ codebook,
                    const float* __restrict__ A,
                    const float* __restrict__ W,
                    const float* __restrict__ bias,
                    const float* __restrict__ gum,
                    float*       __restrict__ ids_out,
                    float*       __restrict__ quant_out,
                    float*       __restrict__ probs_out)
{
    const int grp  = blockIdx.x;
    const int row  = grp >> 2;
    const int g    = grp & 3;
    const int tid  = threadIdx.x;
    const int lane = tid & 31;
    const int warp = tid >> 5;

    const __half* base = g_logits + (size_t)grp * Vx;

    // one uint4 = 8 halves per thread
    uint4 u = *(const uint4*)&base[tid * 8];
    float v[8];
    {
        const __half2* hp = (const __half2*)&u;
        float2 f0 = __half22float2(hp[0]);
        float2 f1 = __half22float2(hp[1]);
        float2 f2 = __half22float2(hp[2]);
        float2 f3 = __half22float2(hp[3]);
        v[0] = f0.x; v[1] = f0.y; v[2] = f1.x; v[3] = f1.y;
        v[4] = f2.x; v[5] = f2.y; v[6] = f3.x; v[7] = f3.y;
    }

    float m1 = v[0], m2 = -3.4e38f;
    int i1 = tid * 8, i2 = -1;
#pragma unroll
    for (int j = 1; j < 8; j++) {
        const int ii = tid * 8 + j;
        if (v[j] > m1) { m2 = m1; i2 = i1; m1 = v[j]; i1 = ii; }
        else if (v[j] > m2) { m2 = v[j]; i2 = ii; }
    }
#pragma unroll
    for (int off = 16; off > 0; off >>= 1) {
        float o1 = __shfl_down_sync(0xffffffffu, m1, off);
        int   oi1 = __shfl_down_sync(0xffffffffu, i1, off);
        float o2 = __shfl_down_sync(0xffffffffu, m2, off);
        int   oi2 = __shfl_down_sync(0xffffffffu, i2, off);
        if (o1 > m1 || (o1 == m1 && oi1 < i1)) {
            float t2 = (m1 > o2 || (m1 == o2 && i1 < oi2)) ? m1 : o2;
            int   ti2 = (m1 > o2 || (m1 == o2 && i1 < oi2)) ? i1 : oi2;
            m1 = o1; i1 = oi1; m2 = t2; i2 = ti2;
        } else {
            if (o1 > m2 || (o1 == m2 && oi1 < i2)) { m2 = o1; i2 = oi1; }
        }
    }

    __shared__ float sw1[4], sw2[4], ssum[4];
    __shared__ int   si1[4], si2[4];
    __shared__ float red_m, red_s, sfix[2];
    __shared__ int   red_i, cand1, cand2, need_fix;

    if (lane == 0) { sw1[warp] = m1; si1[warp] = i1; sw2[warp] = m2; si2[warp] = i2; }
    __syncthreads();
    if (tid == 0) {
        float b1 = sw1[0], b2 = sw2[0]; int j1 = si1[0], j2 = si2[0];
        for (int w = 1; w < 4; w++) {
            float o1 = sw1[w], o2 = sw2[w]; int oi1 = si1[w], oi2 = si2[w];
            if (o1 > b1 || (o1 == b1 && oi1 < j1)) {
                float t2 = (b1 > o2 || (b1 == o2 && j1 < oi2)) ? b1 : o2;
                int   ti2 = (b1 > o2 || (b1 == o2 && j1 < oi2)) ? j1 : oi2;
                b1 = o1; j1 = oi1; b2 = t2; j2 = ti2;
            } else if (o1 > b2 || (o1 == b2 && oi1 < j2)) { b2 = o1; j2 = oi1; }
        }
        red_m = b1; red_i = j1; cand1 = j1; cand2 = j2;
        need_fix = (b1 - b2 < 6e-3f) ? 1 : 0;
    }
    __syncthreads();

    const int pad = pads[row];

    if (need_fix && !pad) {
        const float* arow = A + (size_t)row * Kx;
        for (int cidx = 0; cidx < 2; cidx++) {
            const int vv = (cidx == 0) ? cand1 : cand2;
            const int col = (g << 10) + vv;
            float part = 0.f;
#pragma unroll
            for (int j = 0; j < 8; j++) {
                const int k = tid * 8 + j;
                part = fmaf(arow[k], W[(size_t)k * Nx + col], part);
            }
#pragma unroll
            for (int off = 16; off > 0; off >>= 1)
                part += __shfl_down_sync(0xffffffffu, part, off);
            if (lane == 0) ssum[warp] = part;
            __syncthreads();
            if (tid == 0) {
                float tot = ssum[0] + ssum[1] + ssum[2] + ssum[3];
                sfix[cidx] = (tot + bias[col] + gum[(size_t)grp * Vx + vv]) * INV_TAU;
            }
            __syncthreads();
        }
        if (tid == 0) {
            const float v1 = sfix[0], v2 = sfix[1];
            red_i = (v2 > v1 || (v2 == v1 && cand2 < cand1)) ? cand2 : cand1;
        }
        __syncthreads();
    }

    const float mx = red_m;
    float e[8]; float s = 0.f;
#pragma unroll
    for (int j = 0; j < 8; j++) { e[j] = __expf(v[j] - mx); s += e[j]; }
#pragma unroll
    for (int off = 16; off > 0; off >>= 1)
        s += __shfl_down_sync(0xffffffffu, s, off);
    if (lane == 0) ssum[warp] = s;
    __syncthreads();
    if (tid == 0) red_s = ssum[0] + ssum[1] + ssum[2] + ssum[3];
    __syncthreads();

    const float inv = pad ? 0.f : (1.f / red_s);
    float4 p0, p1;
    p0.x = e[0] * inv; p0.y = e[1] * inv; p0.z = e[2] * inv; p0.w = e[3] * inv;
    p1.x = e[4] * inv; p1.y = e[5] * inv; p1.z = e[6] * inv; p1.w = e[7] * inv;
    *(float4*)&probs_out[(size_t)grp * Vx + tid * 8]     = p0;
    *(float4*)&probs_out[(size_t)grp * Vx + tid * 8 + 4] = p1;

    const int id = red_i;
    const float q = pad ? 0.f : codebook[(((g << 10) + id) << 7) + tid];
    quant_out[(size_t)row * (4 * Dx) + g * Dx + tid] = q;
    if (tid == 0) ids_out[grp] = pad ? -1.0f : (float)id;
}

// ---------------- launch ----------------
extern "C" void kernel_launch(void* const* d_in, const int* in_sizes, int n_in,
                              void* d_out, int out_size)
{
    const float* inputs = (const float*)d_in[0];
    const int*   pads   = (const int*)  d_in[1];
    const float* gum    = (const float*)d_in[2];
    const float* W      = (const float*)d_in[3];
    const float* bias   = (const float*)d_in[4];
    const float* cb     = (const float*)d_in[5];

    float* out       = (float*)d_out;
    float* ids_out   = out;
    float* quant_out = out + (size_t)Mx * 4;
    float* probs_out = quant_out + (size_t)Mx * 4 * Dx;

    cudaFuncSetAttribute(gemm_kernel, cudaFuncAttributeMaxDynamicSharedMemorySize, SMEM_BYTES);

    split_a_kernel<<<(Mx * Kx / 8 + 255) / 256, 256>>>(inputs);
    dim3 wg(Nx / 64, Kx / 64);
    split_w_kernel<<<wg, 256>>>(W);
    dim3 grid(Nx / 64, Mx / 128);
    gemm_kernel<<<grid, NTHREADS, SMEM_BYTES>>>(bias, gum);
    softmax_kernel<<<Mx * 4, 128>>>(pads, cb, inputs, W, bias, gum,
                                    ids_out, quant_out, probs_out);
}

// round 14
// speedup vs baseline: 1.1120x; 1.0108x over previous
#include <cuda_runtime.h>
#include <cuda_fp16.h>
#include <cstdint>

// GumbelSoftmaxVectorQuantizer — round 14
//   * fp32 logits staging restored (round-13 fp16 cost accuracy, saved no time)
//   * GEMM epilogue computes per-group argmax via packed-u64 atomicMax
//     (orderable(float)<<32 | ~idx -> first-occurrence ties), hidden under MMA
//   * softmax no longer reduces max/argmax: 1 LDG for (max,argmax), per-elem
//     near-tie flag + __syncthreads_count gates the rare exact-fp32 fixup
//   * split_a + split_w + stats-clear merged into one prep kernel

static constexpr int Mx = 16384;
static constexpr int Kx = 1024;
static constexpr int Nx = 4096;
static constexpr int Vx = 1024;
static constexpr int Dx = 128;
static constexpr float INV_TAU = 0.5f;
static constexpr float FIX_THRESH = 3e-3f;   // ~10.7 sigma of fp16-GEMM error

__device__ float g_logits[(size_t)Mx * Nx];
__device__ unsigned short g_Ah[(size_t)Mx * Kx];        // fp16 [M][K]
__device__ unsigned short g_Bh[(size_t)Nx * Kx];        // fp16 [N][K] = W^T
__device__ unsigned long long g_stats[(size_t)Mx * 4];  // packed (max, ~argmax) per group

__device__ __forceinline__ uint32_t smem_u32(const void* p) {
    uint32_t a;
    asm("{ .reg .u64 t; cvta.to.shared.u64 t, %1; cvt.u32.u64 %0, t; }" : "=r"(a) : "l"(p));
    return a;
}
__device__ __forceinline__ uint32_t ford(float f) {      // monotone float->uint
    uint32_t b = __float_as_uint(f);
    return (b & 0x80000000u) ? ~b : (b | 0x80000000u);
}
__device__ __forceinline__ float funord(uint32_t u) {    // inverse
    return __uint_as_float((u & 0x80000000u) ? (u ^ 0x80000000u) : ~u);
}

// ---------------- K0: prep (split A, split+transpose W, clear stats) ----------------
__global__ __launch_bounds__(256)
void prep_kernel(const float* __restrict__ A, const float* __restrict__ W) {
    const int bid = blockIdx.x;
    const int tid = threadIdx.x;
    if (bid < 8192) {
        // A -> fp16, row-major
        const size_t idx = ((size_t)bid * 256 + tid) * 8;
        float4 a0 = *(const float4*)&A[idx];
        float4 a1 = *(const float4*)&A[idx + 4];
        float v[8] = {a0.x, a0.y, a0.z, a0.w, a1.x, a1.y, a1.z, a1.w};
        unsigned short h[8];
#pragma unroll
        for (int t = 0; t < 8; t++)
            h[t] = __half_as_ushort(__float2half_rn(v[t]));
        uint4 uh;
        uh.x = h[0] | ((uint32_t)h[1] << 16); uh.y = h[2] | ((uint32_t)h[3] << 16);
        uh.z = h[4] | ((uint32_t)h[5] << 16); uh.w = h[6] | ((uint32_t)h[7] << 16);
        *(uint4*)&g_Ah[idx] = uh;
    } else if (bid < 8192 + 1024) {
        // W tile transpose + fp16
        __shared__ float s[64][65];
        const int q  = bid - 8192;
        const int ct = q >> 6;
        const int n0 = (q & 63) << 6;
        const int k0 = ct * 64;
        for (int i = tid; i < 1024; i += 256) {
            const int kk = i >> 4, n4 = (i & 15) << 2;
            float4 w = *(const float4*)&W[(size_t)(k0 + kk) * Nx + n0 + n4];
            s[kk][n4] = w.x; s[kk][n4 + 1] = w.y; s[kk][n4 + 2] = w.z; s[kk][n4 + 3] = w.w;
        }
        __syncthreads();
        for (int i = tid; i < 512; i += 256) {
            const int nl = i >> 3, j = (i & 7) << 3;
            unsigned short h[8];
#pragma unroll
            for (int t = 0; t < 8; t++)
                h[t] = __half_as_ushort(__float2half_rn(s[j + t][nl]));
            const size_t o = (size_t)(n0 + nl) * Kx + k0 + j;
            uint4 uh;
            uh.x = h[0] | ((uint32_t)h[1] << 16); uh.y = h[2] | ((uint32_t)h[3] << 16);
            uh.z = h[4] | ((uint32_t)h[5] << 16); uh.w = h[6] | ((uint32_t)h[7] << 16);
            *(uint4*)&g_Bh[o] = uh;
        }
    } else {
        // clear stats: 64 blocks x 256 threads x 4 u64 = 65536
        const size_t base = (size_t)(bid - 9216) * 1024 + tid * 4;
#pragma unroll
        for (int t = 0; t < 4; t++) g_stats[base + t] = 0ull;
    }
}

// ---------------- K1: mma.sync fp16 GEMM (128x64 tile, BK=64) ----------------
static constexpr int BK = 64;
static constexpr int STAGES = 3;
static constexpr int RSTRIDE = 72;                    // fp16 per row (144B)
static constexpr int ROW_B = 128;
static constexpr int STAGE_BYTES = 192 * RSTRIDE * 2; // 27648
static constexpr int SMEM_BYTES = STAGES * STAGE_BYTES; // 82944
static constexpr int NCHUNK = Kx / BK;                // 16
static constexpr int NTHREADS = 256;

__device__ __forceinline__ void cp16(uint32_t dst, const void* src) {
    asm volatile("cp.async.cg.shared.global [%0], [%1], 16;" :: "r"(dst), "l"(src) : "memory");
}
__device__ __forceinline__ void cp_commit() {
    asm volatile("cp.async.commit_group;" ::: "memory");
}
__device__ __forceinline__ void cp_wait1() {
    asm volatile("cp.async.wait_group 1;" ::: "memory");
}
__device__ __forceinline__ void ldsm4(uint32_t& r0, uint32_t& r1, uint32_t& r2, uint32_t& r3,
                                      uint32_t addr) {
    asm volatile("ldmatrix.sync.aligned.m8n8.x4.shared.b16 {%0,%1,%2,%3}, [%4];"
                 : "=r"(r0), "=r"(r1), "=r"(r2), "=r"(r3) : "r"(addr));
}
__device__ __forceinline__ void mma_f16(float* c, const uint32_t* a, const uint32_t* b) {
    asm volatile(
        "mma.sync.aligned.m16n8k16.row.col.f32.f16.f16.f32 "
        "{%0,%1,%2,%3}, {%4,%5,%6,%7}, {%8,%9}, {%0,%1,%2,%3};"
        : "+f"(c[0]), "+f"(c[1]), "+f"(c[2]), "+f"(c[3])
        : "r"(a[0]), "r"(a[1]), "r"(a[2]), "r"(a[3]), "r"(b[0]), "r"(b[1]));
}

__global__ __launch_bounds__(NTHREADS, 2)
void gemm_kernel(const float* __restrict__ bias, const float* __restrict__ gum) {
    extern __shared__ char smem[];
    const uint32_t sbase = smem_u32(smem);
    const int tid  = threadIdx.x;
    const int lane = tid & 31;
    const int wid  = tid >> 5;
    const int wm   = wid >> 1;
    const int wn   = wid & 1;
    const int bm   = blockIdx.y * 128;
    const int bn   = blockIdx.x * 64;

    const unsigned short* srcAh = g_Ah + (size_t)bm * Kx;
    const unsigned short* srcBh = g_Bh + (size_t)bn * Kx;

    auto issue_stage = [&](int chunk) {
        const int s = chunk % STAGES;
        const uint32_t stb = sbase + s * STAGE_BYTES;
        const size_t kof = (size_t)chunk * BK;
#pragma unroll
        for (int i = 0; i < 4; i++) {
            const int idx = tid + i * 256;
            const int r = idx >> 3, c = idx & 7;
            cp16(stb + (uint32_t)(r * 144 + c * 16),
                 srcAh + (size_t)r * Kx + kof + c * 8);
        }
#pragma unroll
        for (int i = 4; i < 6; i++) {
            const int idx = tid + i * 256;
            const int r = idx >> 3, c = idx & 7;
            cp16(stb + (uint32_t)(r * 144 + c * 16),
                 srcBh + (size_t)(r - 128) * Kx + kof + c * 8);
        }
        cp_commit();
    };

    float acc[2][4][4];
#pragma unroll
    for (int i = 0; i < 2; i++)
#pragma unroll
        for (int j = 0; j < 4; j++)
#pragma unroll
            for (int q = 0; q < 4; q++) acc[i][j][q] = 0.f;

    issue_stage(0); issue_stage(1);

    const int lrow = lane & 15;
    const int lcol = (lane >> 4) * 8;

#pragma unroll 1
    for (int ch = 0; ch < NCHUNK; ch++) {
        cp_wait1();
        __syncthreads();
        if (ch + 2 < NCHUNK) issue_stage(ch + 2);

        const uint32_t stb = sbase + (ch % STAGES) * STAGE_BYTES;

#pragma unroll
        for (int ks = 0; ks < 4; ks++) {
            const int kk = ks * 16;
            uint32_t ah[2][4], bh[4][2];
#pragma unroll
            for (int mf = 0; mf < 2; mf++) {
                const int row = wm * 32 + mf * 16 + lrow;
                const uint32_t off = (uint32_t)(row * RSTRIDE + kk + lcol) * 2;
                ldsm4(ah[mf][0], ah[mf][1], ah[mf][2], ah[mf][3], stb + off);
            }
#pragma unroll
            for (int np = 0; np < 2; np++) {
                const int row = ROW_B + wn * 32 + np * 16 + lrow;
                const uint32_t off = (uint32_t)(row * RSTRIDE + kk + lcol) * 2;
                uint32_t r0, r1, r2, r3;
                ldsm4(r0, r1, r2, r3, stb + off);
                bh[2 * np][0] = r0; bh[2 * np][1] = r2;
                bh[2 * np + 1][0] = r1; bh[2 * np + 1][1] = r3;
            }
#pragma unroll
            for (int mf = 0; mf < 2; mf++)
#pragma unroll
                for (int nf = 0; nf < 4; nf++)
                    mma_f16(acc[mf][nf], ah[mf], bh[nf]);
        }
    }

    // epilogue: o = (acc + bias + gumbel) * INV_TAU -> g_logits (fp32),
    //           overwrite acc with o for the stats pass
    const int er = lane >> 2;
    const int ec = (lane & 3) * 2;
#pragma unroll
    for (int mf = 0; mf < 2; mf++) {
#pragma unroll
        for (int nf = 0; nf < 4; nf++) {
            const int col = bn + wn * 32 + nf * 8 + ec;
            const float2 bb = *(const float2*)&bias[col];
#pragma unroll
            for (int h = 0; h < 2; h++) {
                const int row = bm + wm * 32 + mf * 16 + er + h * 8;
                const size_t go = (size_t)row * Nx + col;
                const float2 g = *(const float2*)&gum[go];
                float2 o;
                o.x = (acc[mf][nf][2 * h]     + bb.x + g.x) * INV_TAU;
                o.y = (acc[mf][nf][2 * h + 1] + bb.y + g.y) * INV_TAU;
                *(float2*)&g_logits[go] = o;
                acc[mf][nf][2 * h]     = o.x;
                acc[mf][nf][2 * h + 1] = o.y;
            }
        }
    }

    // per-(row, group) argmax contribution via packed u64 atomicMax
    const int g4 = bn >> 10;                 // group of this 64-col tile
    const int vbase = (bn & 1023) + wn * 32; // V-index base of this warp's cols
#pragma unroll
    for (int mf = 0; mf < 2; mf++) {
#pragma unroll
        for (int h = 0; h < 2; h++) {
            float bv = acc[mf][0][2 * h];
            int   bc = vbase + ec;
#pragma unroll
            for (int nf = 0; nf < 4; nf++) {
#pragma unroll
                for (int e = 0; e < 2; e++) {
                    if (nf == 0 && e == 0) continue;
                    const float val = acc[mf][nf][2 * h + e];
                    const int   vc  = vbase + nf * 8 + ec + e;
                    if (val > bv) { bv = val; bc = vc; }   // ascending -> first occurrence
                }
            }
            unsigned long long key =
                ((unsigned long long)ford(bv) << 32) | (uint32_t)(~bc);
            // quad reduce: lanes er*4 + {0..3} share the same row
#pragma unroll
            for (int sft = 1; sft <= 2; sft <<= 1) {
                unsigned long long ok = __shfl_xor_sync(0xffffffffu, key, sft);
                if (ok > key) key = ok;
            }
            if ((lane & 3) == 0) {
                const int row = bm + wm * 32 + mf * 16 + er + h * 8;
                atomicMax(&g_stats[(size_t)row * 4 + g4], key);
            }
        }
    }
}

// ---------------- K2: softmax (max/argmax precomputed) ----------------
__global__ __launch_bounds__(128)
void softmax_kernel(const int*   __restrict__ pads,
                    const float* __restrict__ codebook,
                    const float* __restrict__ A,
                    const float* __restrict__ W,
                    const float* __restrict__ bias,
                    const float* __restrict__ gum,
                    float*       __restrict__ ids_out,
                    float*       __restrict__ quant_out,
                    float*       __restrict__ probs_out)
{
    const int grp  = blockIdx.x;
    const int row  = grp >> 2;
    const int g    = grp & 3;
    const int tid  = threadIdx.x;
    const int lane = tid & 31;
    const int warp = tid >> 5;

    __shared__ float ssum[4];
    __shared__ float red_s, sbv;
    __shared__ int   scnt, sbi;
    __shared__ int   scand[7];

    const unsigned long long key = g_stats[grp];
    const float gmax = funord((uint32_t)(key >> 32));
    const int   id0  = (int)(~(uint32_t)key) & 1023;

    const float* base = g_logits + (size_t)grp * Vx;
    float v[8];
    *(float4*)&v[0] = *(const float4*)&base[tid * 8];
    *(float4*)&v[4] = *(const float4*)&base[tid * 8 + 4];

    if (tid == 0) scnt = 0;

    // near-tie flag (excluding the argmax element itself)
    int hasOther = 0;
#pragma unroll
    for (int j = 0; j < 8; j++) {
        const int idx = tid * 8 + j;
        hasOther |= ((gmax - v[j] < FIX_THRESH) && (idx != id0)) ? 1 : 0;
    }
    const int nOther = __syncthreads_count(hasOther);

    if (hasOther) {
#pragma unroll
        for (int j = 0; j < 8; j++) {
            const int idx = tid * 8 + j;
            if ((gmax - v[j] < FIX_THRESH) && (idx != id0)) {
                const int p = atomicAdd(&scnt, 1);
                if (p < 7) scand[p] = idx;
            }
        }
    }

    // exp + sum
    float e[8]; float s = 0.f;
#pragma unroll
    for (int j = 0; j < 8; j++) { e[j] = __expf(v[j] - gmax); s += e[j]; }
#pragma unroll
    for (int off = 16; off > 0; off >>= 1)
        s += __shfl_down_sync(0xffffffffu, s, off);
    if (lane == 0) ssum[warp] = s;
    __syncthreads();                       // also makes scnt/scand visible
    if (tid == 0) red_s = ssum[0] + ssum[1] + ssum[2] + ssum[3];
    __syncthreads();

    const int pad = pads[row];
    int id = id0;

    // rare exact fp32 fixup over all near-tie candidates
    if (nOther > 0 && !pad) {
        const int ncand = (scnt < 7) ? scnt : 7;
        const float* arow = A + (size_t)row * Kx;
#pragma unroll 1
        for (int c = -1; c < ncand; c++) {
            const int vv = (c < 0) ? id0 : scand[c];
            const int col = (g << 10) + vv;
            float part = 0.f;
#pragma unroll
            for (int j = 0; j < 8; j++) {
                const int k = tid * 8 + j;
                part = fmaf(arow[k], W[(size_t)k * Nx + col], part);
            }
#pragma unroll
            for (int off = 16; off > 0; off >>= 1)
                part += __shfl_down_sync(0xffffffffu, part, off);
            if (lane == 0) ssum[warp] = part;
            __syncthreads();
            if (tid == 0) {
                const float tot = ssum[0] + ssum[1] + ssum[2] + ssum[3];
                const float exact = (tot + bias[col] + gum[(size_t)grp * Vx + vv]) * INV_TAU;
                if (c < 0) { sbv = exact; sbi = vv; }
                else if (exact > sbv || (exact == sbv && vv < sbi)) { sbv = exact; sbi = vv; }
            }
            __syncthreads();
        }
        id = sbi;
    }

    const float inv = pad ? 0.f : (1.f / red_s);
    float4 p0, p1;
    p0.x = e[0] * inv; p0.y = e[1] * inv; p0.z = e[2] * inv; p0.w = e[3] * inv;
    p1.x = e[4] * inv; p1.y = e[5] * inv; p1.z = e[6] * inv; p1.w = e[7] * inv;
    *(float4*)&probs_out[(size_t)grp * Vx + tid * 8]     = p0;
    *(float4*)&probs_out[(size_t)grp * Vx + tid * 8 + 4] = p1;

    const float q = pad ? 0.f : codebook[(((g << 10) + id) << 7) + tid];
    quant_out[(size_t)row * (4 * Dx) + g * Dx + tid] = q;
    if (tid == 0) ids_out[grp] = pad ? -1.0f : (float)id;
}

// ---------------- launch ----------------
extern "C" void kernel_launch(void* const* d_in, const int* in_sizes, int n_in,
                              void* d_out, int out_size)
{
    const float* inputs = (const float*)d_in[0];
    const int*   pads   = (const int*)  d_in[1];
    const float* gum    = (const float*)d_in[2];
    const float* W      = (const float*)d_in[3];
    const float* bias   = (const float*)d_in[4];
    const float* cb     = (const float*)d_in[5];

    float* out       = (float*)d_out;
    float* ids_out   = out;
    float* quant_out = out + (size_t)Mx * 4;
    float* probs_out = quant_out + (size_t)Mx * 4 * Dx;

    cudaFuncSetAttribute(gemm_kernel, cudaFuncAttributeMaxDynamicSharedMemorySize, SMEM_BYTES);

    prep_kernel<<<8192 + 1024 + 64, 256>>>(inputs, W);
    dim3 grid(Nx / 64, Mx / 128);
    gemm_kernel<<<grid, NTHREADS, SMEM_BYTES>>>(bias, gum);
    softmax_kernel<<<Mx * 4, 128>>>(pads, cb, inputs, W, bias, gum,
                                    ids_out, quant_out, probs_out);
}

// round 15
// speedup vs baseline: 1.7620x; 1.5846x over previous
#include <cuda_runtime.h>
#include <cuda_fp16.h>
#include <cstdint>

// GumbelSoftmaxVectorQuantizer — round 15: padded-row compaction
//   ~50% of rows are padded and their logits are never used. A 1-block scan
//   compacts non-padded rows; the GEMM runs on M'≈8192 rows (half the waves),
//   epilogue scatters to original rows via rowmap; softmax takes a
//   write-zeros fast path for padded groups. Numerics of non-padded rows are
//   bit-identical to round 14 (row placement doesn't affect per-row dots).

static constexpr int Mx = 16384;
static constexpr int Kx = 1024;
static constexpr int Nx = 4096;
static constexpr int Vx = 1024;
static constexpr int Dx = 128;
static constexpr float INV_TAU = 0.5f;
static constexpr float FIX_THRESH = 3e-3f;

__device__ float g_logits[(size_t)Mx * Nx];             // by ORIGINAL row
__device__ unsigned short g_Ac[(size_t)Mx * Kx];        // fp16 compact A
__device__ unsigned short g_Bh[(size_t)Nx * Kx];        // fp16 [N][K] = W^T
__device__ unsigned long long g_stats[(size_t)Mx * 4];  // by original row
__device__ int g_cidx[Mx];                              // row -> compact or -1
__device__ int g_rowmap[Mx];                            // compact -> row
__device__ int g_Mp;                                    // # nonpad rows

__device__ __forceinline__ uint32_t smem_u32(const void* p) {
    uint32_t a;
    asm("{ .reg .u64 t; cvta.to.shared.u64 t, %1; cvt.u32.u64 %0, t; }" : "=r"(a) : "l"(p));
    return a;
}
__device__ __forceinline__ uint32_t ford(float f) {
    uint32_t b = __float_as_uint(f);
    return (b & 0x80000000u) ? ~b : (b | 0x80000000u);
}
__device__ __forceinline__ float funord(uint32_t u) {
    return __uint_as_float((u & 0x80000000u) ? (u ^ 0x80000000u) : ~u);
}

// ---------------- K-1: scan (1 block, 512 threads) ----------------
__global__ __launch_bounds__(512)
void scan_kernel(const int* __restrict__ pads) {
    __shared__ int part[512];
    const int t = threadIdx.x;
    int flags[32];
    int cnt = 0;
#pragma unroll
    for (int i = 0; i < 32; i++) {
        flags[i] = (pads[t * 32 + i] == 0) ? 1 : 0;
        cnt += flags[i];
    }
    part[t] = cnt;
    __syncthreads();
    // inclusive Hillis-Steele scan over 512 partials
    for (int off = 1; off < 512; off <<= 1) {
        const int mine = part[t];
        const int other = (t >= off) ? part[t - off] : 0;
        __syncthreads();
        part[t] = mine + other;
        __syncthreads();
    }
    int base = part[t] - cnt;   // exclusive
#pragma unroll
    for (int i = 0; i < 32; i++) {
        const int row = t * 32 + i;
        if (flags[i]) { g_cidx[row] = base; g_rowmap[base] = row; base++; }
        else          { g_cidx[row] = -1; }
    }
    const int total = part[511];
    if (t == 0) g_Mp = total;
    // zero-fill compact-A tail to next multiple of 128 rows
    const int padto = (total + 127) & ~127;
    const uint4 z = make_uint4(0u, 0u, 0u, 0u);
    for (int r = total + t; r < padto; r += 512) {
        uint4* dst = (uint4*)&g_Ac[(size_t)r << 10];
#pragma unroll
        for (int q = 0; q < 128; q++) dst[q] = z;
    }
}

// ---------------- K0: prep (compact-split A, split+transpose W, clear stats) ----------------
__global__ __launch_bounds__(256)
void prep_kernel(const float* __restrict__ A, const float* __restrict__ W) {
    const int bid = blockIdx.x;
    const int tid = threadIdx.x;
    if (bid < 8192) {
        const size_t idx = ((size_t)bid * 256 + tid) * 8;
        const int row = (int)(idx >> 10);
        const int c = g_cidx[row];
        if (c < 0) return;
        float4 a0 = *(const float4*)&A[idx];
        float4 a1 = *(const float4*)&A[idx + 4];
        float v[8] = {a0.x, a0.y, a0.z, a0.w, a1.x, a1.y, a1.z, a1.w};
        unsigned short h[8];
#pragma unroll
        for (int t2 = 0; t2 < 8; t2++)
            h[t2] = __half_as_ushort(__float2half_rn(v[t2]));
        uint4 uh;
        uh.x = h[0] | ((uint32_t)h[1] << 16); uh.y = h[2] | ((uint32_t)h[3] << 16);
        uh.z = h[4] | ((uint32_t)h[5] << 16); uh.w = h[6] | ((uint32_t)h[7] << 16);
        *(uint4*)&g_Ac[((size_t)c << 10) + (idx & 1023)] = uh;
    } else if (bid < 8192 + 1024) {
        __shared__ float s[64][65];
        const int q  = bid - 8192;
        const int ct = q >> 6;
        const int n0 = (q & 63) << 6;
        const int k0 = ct * 64;
        for (int i = tid; i < 1024; i += 256) {
            const int kk = i >> 4, n4 = (i & 15) << 2;
            float4 w = *(const float4*)&W[(size_t)(k0 + kk) * Nx + n0 + n4];
            s[kk][n4] = w.x; s[kk][n4 + 1] = w.y; s[kk][n4 + 2] = w.z; s[kk][n4 + 3] = w.w;
        }
        __syncthreads();
        for (int i = tid; i < 512; i += 256) {
            const int nl = i >> 3, j = (i & 7) << 3;
            unsigned short h[8];
#pragma unroll
            for (int t2 = 0; t2 < 8; t2++)
                h[t2] = __half_as_ushort(__float2half_rn(s[j + t2][nl]));
            const size_t o = (size_t)(n0 + nl) * Kx + k0 + j;
            uint4 uh;
            uh.x = h[0] | ((uint32_t)h[1] << 16); uh.y = h[2] | ((uint32_t)h[3] << 16);
            uh.z = h[4] | ((uint32_t)h[5] << 16); uh.w = h[6] | ((uint32_t)h[7] << 16);
            *(uint4*)&g_Bh[o] = uh;
        }
    } else {
        const size_t base = (size_t)(bid - 9216) * 1024 + tid * 4;
#pragma unroll
        for (int t2 = 0; t2 < 4; t2++) g_stats[base + t2] = 0ull;
    }
}

// ---------------- K1: mma.sync fp16 GEMM (128x64 tile, BK=64, compact M) ----------------
static constexpr int BK = 64;
static constexpr int STAGES = 3;
static constexpr int RSTRIDE = 72;
static constexpr int ROW_B = 128;
static constexpr int STAGE_BYTES = 192 * RSTRIDE * 2;
static constexpr int SMEM_BYTES = STAGES * STAGE_BYTES;
static constexpr int NCHUNK = Kx / BK;
static constexpr int NTHREADS = 256;

__device__ __forceinline__ void cp16(uint32_t dst, const void* src) {
    asm volatile("cp.async.cg.shared.global [%0], [%1], 16;" :: "r"(dst), "l"(src) : "memory");
}
__device__ __forceinline__ void cp_commit() {
    asm volatile("cp.async.commit_group;" ::: "memory");
}
__device__ __forceinline__ void cp_wait1() {
    asm volatile("cp.async.wait_group 1;" ::: "memory");
}
__device__ __forceinline__ void ldsm4(uint32_t& r0, uint32_t& r1, uint32_t& r2, uint32_t& r3,
                                      uint32_t addr) {
    asm volatile("ldmatrix.sync.aligned.m8n8.x4.shared.b16 {%0,%1,%2,%3}, [%4];"
                 : "=r"(r0), "=r"(r1), "=r"(r2), "=r"(r3) : "r"(addr));
}
__device__ __forceinline__ void mma_f16(float* c, const uint32_t* a, const uint32_t* b) {
    asm volatile(
        "mma.sync.aligned.m16n8k16.row.col.f32.f16.f16.f32 "
        "{%0,%1,%2,%3}, {%4,%5,%6,%7}, {%8,%9}, {%0,%1,%2,%3};"
        : "+f"(c[0]), "+f"(c[1]), "+f"(c[2]), "+f"(c[3])
        : "r"(a[0]), "r"(a[1]), "r"(a[2]), "r"(a[3]), "r"(b[0]), "r"(b[1]));
}

__global__ __launch_bounds__(NTHREADS, 2)
void gemm_kernel(const float* __restrict__ bias, const float* __restrict__ gum) {
    const int bm = blockIdx.y * 128;
    const int Mp = g_Mp;
    if (bm >= Mp) return;                       // compacted: half the CTAs exit

    extern __shared__ char smem[];
    const uint32_t sbase = smem_u32(smem);
    const int tid  = threadIdx.x;
    const int lane = tid & 31;
    const int wid  = tid >> 5;
    const int wm   = wid >> 1;
    const int wn   = wid & 1;
    const int bn   = blockIdx.x * 64;

    const unsigned short* srcAh = g_Ac + (size_t)bm * Kx;
    const unsigned short* srcBh = g_Bh + (size_t)bn * Kx;

    auto issue_stage = [&](int chunk) {
        const int s = chunk % STAGES;
        const uint32_t stb = sbase + s * STAGE_BYTES;
        const size_t kof = (size_t)chunk * BK;
#pragma unroll
        for (int i = 0; i < 4; i++) {
            const int idx = tid + i * 256;
            const int r = idx >> 3, c = idx & 7;
            cp16(stb + (uint32_t)(r * 144 + c * 16),
                 srcAh + (size_t)r * Kx + kof + c * 8);
        }
#pragma unroll
        for (int i = 4; i < 6; i++) {
            const int idx = tid + i * 256;
            const int r = idx >> 3, c = idx & 7;
            cp16(stb + (uint32_t)(r * 144 + c * 16),
                 srcBh + (size_t)(r - 128) * Kx + kof + c * 8);
        }
        cp_commit();
    };

    float acc[2][4][4];
#pragma unroll
    for (int i = 0; i < 2; i++)
#pragma unroll
        for (int j = 0; j < 4; j++)
#pragma unroll
            for (int q = 0; q < 4; q++) acc[i][j][q] = 0.f;

    issue_stage(0); issue_stage(1);

    const int lrow = lane & 15;
    const int lcol = (lane >> 4) * 8;

#pragma unroll 1
    for (int ch = 0; ch < NCHUNK; ch++) {
        cp_wait1();
        __syncthreads();
        if (ch + 2 < NCHUNK) issue_stage(ch + 2);

        const uint32_t stb = sbase + (ch % STAGES) * STAGE_BYTES;

#pragma unroll
        for (int ks = 0; ks < 4; ks++) {
            const int kk = ks * 16;
            uint32_t ah[2][4], bh[4][2];
#pragma unroll
            for (int mf = 0; mf < 2; mf++) {
                const int row = wm * 32 + mf * 16 + lrow;
                const uint32_t off = (uint32_t)(row * RSTRIDE + kk + lcol) * 2;
                ldsm4(ah[mf][0], ah[mf][1], ah[mf][2], ah[mf][3], stb + off);
            }
#pragma unroll
            for (int np = 0; np < 2; np++) {
                const int row = ROW_B + wn * 32 + np * 16 + lrow;
                const uint32_t off = (uint32_t)(row * RSTRIDE + kk + lcol) * 2;
                uint32_t r0, r1, r2, r3;
                ldsm4(r0, r1, r2, r3, stb + off);
                bh[2 * np][0] = r0; bh[2 * np][1] = r2;
                bh[2 * np + 1][0] = r1; bh[2 * np + 1][1] = r3;
            }
#pragma unroll
            for (int mf = 0; mf < 2; mf++)
#pragma unroll
                for (int nf = 0; nf < 4; nf++)
                    mma_f16(acc[mf][nf], ah[mf], bh[nf]);
        }
    }

    // epilogue: scatter to original rows; skip rows beyond Mp
    const int er = lane >> 2;
    const int ec = (lane & 3) * 2;
    const int g4 = bn >> 10;
    const int vbase = (bn & 1023) + wn * 32;

#pragma unroll
    for (int mf = 0; mf < 2; mf++) {
#pragma unroll
        for (int h = 0; h < 2; h++) {
            const int rowc = bm + wm * 32 + mf * 16 + er + h * 8;
            if (rowc >= Mp) continue;
            const int orow = g_rowmap[rowc];

            float vmax = -3.4e38f; int vidx = 0;
#pragma unroll
            for (int nf = 0; nf < 4; nf++) {
                const int col = bn + wn * 32 + nf * 8 + ec;
                const float2 bb = *(const float2*)&bias[col];
                const size_t go = (size_t)orow * Nx + col;
                const float2 g = *(const float2*)&gum[go];
                float2 o;
                o.x = (acc[mf][nf][2 * h]     + bb.x + g.x) * INV_TAU;
                o.y = (acc[mf][nf][2 * h + 1] + bb.y + g.y) * INV_TAU;
                *(float2*)&g_logits[go] = o;
                const int vc = vbase + nf * 8 + ec;
                if (o.x > vmax) { vmax = o.x; vidx = vc; }
                if (o.y > vmax) { vmax = o.y; vidx = vc + 1; }
            }
            unsigned long long key =
                ((unsigned long long)ford(vmax) << 32) | (uint32_t)(~vidx);
#pragma unroll
            for (int sft = 1; sft <= 2; sft <<= 1) {
                unsigned long long ok = __shfl_xor_sync(0xffffffffu, key, sft);
                if (ok > key) key = ok;
            }
            if ((lane & 3) == 0)
                atomicMax(&g_stats[(size_t)orow * 4 + g4], key);
        }
    }
}

// ---------------- K2: softmax (padded fast path + precomputed argmax) ----------------
__global__ __launch_bounds__(128)
void softmax_kernel(const int*   __restrict__ pads,
                    const float* __restrict__ codebook,
                    const float* __restrict__ A,
                    const float* __restrict__ W,
                    const float* __restrict__ bias,
                    const float* __restrict__ gum,
                    float*       __restrict__ ids_out,
                    float*       __restrict__ quant_out,
                    float*       __restrict__ probs_out)
{
    const int grp  = blockIdx.x;
    const int row  = grp >> 2;
    const int g    = grp & 3;
    const int tid  = threadIdx.x;
    const int lane = tid & 31;
    const int warp = tid >> 5;

    const int pad = pads[row];
    if (pad) {
        const float4 z = make_float4(0.f, 0.f, 0.f, 0.f);
        *(float4*)&probs_out[(size_t)grp * Vx + tid * 8]     = z;
        *(float4*)&probs_out[(size_t)grp * Vx + tid * 8 + 4] = z;
        quant_out[(size_t)row * (4 * Dx) + g * Dx + tid] = 0.f;
        if (tid == 0) ids_out[grp] = -1.0f;
        return;
    }

    __shared__ float ssum[4];
    __shared__ float red_s, sbv;
    __shared__ int   scnt, sbi;
    __shared__ int   scand[7];

    const unsigned long long key = g_stats[grp];
    const float gmax = funord((uint32_t)(key >> 32));
    const int   id0  = (int)(~(uint32_t)key) & 1023;

    const float* base = g_logits + (size_t)grp * Vx;
    float v[8];
    *(float4*)&v[0] = *(const float4*)&base[tid * 8];
    *(float4*)&v[4] = *(const float4*)&base[tid * 8 + 4];

    if (tid == 0) scnt = 0;

    int hasOther = 0;
#pragma unroll
    for (int j = 0; j < 8; j++) {
        const int idx = tid * 8 + j;
        hasOther |= ((gmax - v[j] < FIX_THRESH) && (idx != id0)) ? 1 : 0;
    }
    const int nOther = __syncthreads_count(hasOther);

    if (hasOther) {
#pragma unroll
        for (int j = 0; j < 8; j++) {
            const int idx = tid * 8 + j;
            if ((gmax - v[j] < FIX_THRESH) && (idx != id0)) {
                const int p = atomicAdd(&scnt, 1);
                if (p < 7) scand[p] = idx;
            }
        }
    }

    float e[8]; float s = 0.f;
#pragma unroll
    for (int j = 0; j < 8; j++) { e[j] = __expf(v[j] - gmax); s += e[j]; }
#pragma unroll
    for (int off = 16; off > 0; off >>= 1)
        s += __shfl_down_sync(0xffffffffu, s, off);
    if (lane == 0) ssum[warp] = s;
    __syncthreads();
    if (tid == 0) red_s = ssum[0] + ssum[1] + ssum[2] + ssum[3];
    __syncthreads();

    int id = id0;
    if (nOther > 0) {
        const int ncand = (scnt < 7) ? scnt : 7;
        const float* arow = A + (size_t)row * Kx;
#pragma unroll 1
        for (int c = -1; c < ncand; c++) {
            const int vv = (c < 0) ? id0 : scand[c];
            const int col = (g << 10) + vv;
            float part = 0.f;
#pragma unroll
            for (int j = 0; j < 8; j++) {
                const int k = tid * 8 + j;
                part = fmaf(arow[k], W[(size_t)k * Nx + col], part);
            }
#pragma unroll
            for (int off = 16; off > 0; off >>= 1)
                part += __shfl_down_sync(0xffffffffu, part, off);
            if (lane == 0) ssum[warp] = part;
            __syncthreads();
            if (tid == 0) {
                const float tot = ssum[0] + ssum[1] + ssum[2] + ssum[3];
                const float exact = (tot + bias[col] + gum[(size_t)grp * Vx + vv]) * INV_TAU;
                if (c < 0) { sbv = exact; sbi = vv; }
                else if (exact > sbv || (exact == sbv && vv < sbi)) { sbv = exact; sbi = vv; }
            }
            __syncthreads();
        }
        id = sbi;
    }

    const float inv = 1.f / red_s;
    float4 p0, p1;
    p0.x = e[0] * inv; p0.y = e[1] * inv; p0.z = e[2] * inv; p0.w = e[3] * inv;
    p1.x = e[4] * inv; p1.y = e[5] * inv; p1.z = e[6] * inv; p1.w = e[7] * inv;
    *(float4*)&probs_out[(size_t)grp * Vx + tid * 8]     = p0;
    *(float4*)&probs_out[(size_t)grp * Vx + tid * 8 + 4] = p1;

    quant_out[(size_t)row * (4 * Dx) + g * Dx + tid] =
        codebook[(((g << 10) + id) << 7) + tid];
    if (tid == 0) ids_out[grp] = (float)id;
}

// ---------------- launch ----------------
extern "C" void kernel_launch(void* const* d_in, const int* in_sizes, int n_in,
                              void* d_out, int out_size)
{
    const float* inputs = (const float*)d_in[0];
    const int*   pads   = (const int*)  d_in[1];
    const float* gum    = (const float*)d_in[2];
    const float* W      = (const float*)d_in[3];
    const float* bias   = (const float*)d_in[4];
    const float* cb     = (const float*)d_in[5];

    float* out       = (float*)d_out;
    float* ids_out   = out;
    float* quant_out = out + (size_t)Mx * 4;
    float* probs_out = quant_out + (size_t)Mx * 4 * Dx;

    cudaFuncSetAttribute(gemm_kernel, cudaFuncAttributeMaxDynamicSharedMemorySize, SMEM_BYTES);

    scan_kernel<<<1, 512>>>(pads);
    prep_kernel<<<8192 + 1024 + 64, 256>>>(inputs, W);
    dim3 grid(Nx / 64, Mx / 128);
    gemm_kernel<<<grid, NTHREADS, SMEM_BYTES>>>(bias, gum);
    softmax_kernel<<<Mx * 4, 128>>>(pads, cb, inputs, W, bias, gum,
                                    ids_out, quant_out, probs_out);
}